// round 16
// baseline (speedup 1.0000x reference)
#include <cuda_runtime.h>
#include <cuda_bf16.h>
#include <cstdint>

#define N_NODES_MAX 50000
#define E_MAX 1600000
#define FEAT 300
#define XB_PAD 304              // padded bf16 row (38 uint4)
#define HID 256
#define NFLAG_MAX ((N_NODES_MAX + 63) / 64)

// ---------------- device scratch ----------------
__device__ int   g_degi[N_NODES_MAX];
__device__ int   g_off [N_NODES_MAX + 1];
__device__ int   g_cur [N_NODES_MAX];
__device__ int   g_srcs[E_MAX];
__device__ volatile int g_bsum[256];
__device__ int   g_scnt[1];
__device__ int   g_done[1];
__device__ int   g_flag[NFLAG_MAX];
__device__ __align__(16) float g_dis [N_NODES_MAX];
__device__ __align__(16) float g_dinv[N_NODES_MAX];
__device__ __align__(16) __nv_bfloat16 g_xb [N_NODES_MAX * XB_PAD];  // x bf16 padded
__device__ __align__(16) __nv_bfloat16 g_yb [N_NODES_MAX * XB_PAD];  // y = dis*agg+dinv*x
__device__ __align__(16) __nv_bfloat16 g_sfb[N_NODES_MAX * 2 * HID]; // comb bf16
__device__ __align__(16) __nv_bfloat16 g_wb2[544 * 256];             // QK weights + u_hi + u_lo
__device__ __align__(16) __nv_bfloat16 g_wg [512 * 320];             // block-diag GCN W bf16
__device__ __align__(16) float g_u   [8 * 256];
__device__ __align__(16) float g_c   [8];
__device__ float g_konst[1];
__device__ float g_acc [1];

// ---------------- helpers ----------------
__device__ __forceinline__ float2 bf2_to_f2(uint32_t u) {
    float2 r;
    r.x = __uint_as_float(u << 16);
    r.y = __uint_as_float(u & 0xffff0000u);
    return r;
}
__device__ __forceinline__ uint32_t f2_to_bf2(float a, float b) {
    __nv_bfloat162 p = __float22bfloat162_rn(make_float2(a, b));
    return *reinterpret_cast<uint32_t*>(&p);
}
__device__ __forceinline__ uint32_t smem_u32(const void* p) {
    uint32_t a;
    asm("{ .reg .u64 t; cvta.to.shared.u64 t, %1; cvt.u32.u64 %0, t; }"
        : "=r"(a) : "l"(p));
    return a;
}
__device__ __forceinline__ void ldsm4(uint32_t& r0, uint32_t& r1,
                                      uint32_t& r2, uint32_t& r3, uint32_t addr) {
    asm volatile("ldmatrix.sync.aligned.m8n8.x4.shared.b16 {%0,%1,%2,%3}, [%4];"
                 : "=r"(r0), "=r"(r1), "=r"(r2), "=r"(r3) : "r"(addr));
}
__device__ __forceinline__ void mma16816(float* d, const uint32_t* a,
                                         uint32_t b0, uint32_t b1) {
    asm volatile(
        "mma.sync.aligned.m16n8k16.row.col.f32.bf16.bf16.f32 "
        "{%0,%1,%2,%3}, {%4,%5,%6,%7}, {%8,%9}, {%0,%1,%2,%3};"
        : "+f"(d[0]), "+f"(d[1]), "+f"(d[2]), "+f"(d[3])
        : "r"(a[0]), "r"(a[1]), "r"(a[2]), "r"(a[3]), "r"(b0), "r"(b1));
}
__device__ __forceinline__ void cp16(uint32_t smem_dst, const void* gsrc) {
    asm volatile("cp.async.cg.shared.global [%0], [%1], 16;"
                 :: "r"(smem_dst), "l"(gsrc) : "memory");
}
#define CP_COMMIT() asm volatile("cp.async.commit_group;" ::: "memory")
#define CP_WAIT(N)  asm volatile("cp.async.wait_group %0;" :: "n"(N) : "memory")

// ---------------- phase 0: zero ∥ prep  (block-range fusion) ----------------
__global__ void k_init(const float* __restrict__ ipw, const float* __restrict__ ipb,
                       const float* __restrict__ opw, const float* __restrict__ opb,
                       const float* __restrict__ ow,  const float* __restrict__ ob,
                       int n, int nzb) {
    int t = threadIdx.x;
    if ((int)blockIdx.x < nzb) {
        int i = blockIdx.x * 256 + t;
        if (i < n) g_degi[i] = 0;
        if (i < NFLAG_MAX) g_flag[i] = 0;
        if (i == 0) { g_acc[0] = 0.f; g_done[0] = 0; g_scnt[0] = 0; }
        return;
    }
    // ---- prep (single block) ----
    __shared__ float vout[256];
    float acc = 0.f;
    for (int j = 0; j < 256; j++) acc += opw[j * 256 + t] * ow[j];
    vout[t] = acc;
    __syncthreads();
    #pragma unroll
    for (int h = 0; h < 8; h++) {
        float a = 0.f;
        #pragma unroll 8
        for (int d = 0; d < 32; d++)
            a += ipw[(512 + h * 32 + d) * 256 + t] * vout[h * 32 + d];
        g_u[h * 256 + t] = a;
    }
    if (t < 8) {
        float c = 0.f;
        for (int d = 0; d < 32; d++) c += ipb[512 + t * 32 + d] * vout[t * 32 + d];
        g_c[t] = c;
    }
    if (t == 0) {
        float c = 0.f;
        for (int j = 0; j < 256; j++) c += opb[j] * ow[j];
        g_konst[0] = c + ob[0];
    }
}

// ---------------- phase 1: deg ∥ xconv ----------------
__global__ void k_front(const int* __restrict__ ei, const float* __restrict__ x,
                        int E, int n, int ndeg) {
    int t = threadIdx.x;
    if ((int)blockIdx.x < ndeg) {
        int i = blockIdx.x * 256 + t;
        if (i < E) atomicAdd(&g_degi[ei[E + i]], 1);
        return;
    }
    int j = (blockIdx.x - ndeg) * 256 + t;
    if (j >= n * 152) return;
    int row = j / 152, p = j % 152;
    uint32_t v = 0;
    if (p < 150) {
        float2 f = *reinterpret_cast<const float2*>(&x[row * FEAT + 2 * p]);
        v = f2_to_bf2(f.x, f.y);
    }
    *reinterpret_cast<uint32_t*>(&g_xb[row * XB_PAD + 2 * p]) = v;
}

// ---------------- phase 2: single-kernel scan (counter-synchronized) --------
// All nb (<=196) blocks are co-resident (256 thr, ~2KB smem), so the
// publish-then-spin pattern cannot deadlock. Each block: partial sum +
// normalizers -> publish bsum -> spin until all published -> offsets.
__global__ void k_scan(int nb, int n) {
    __shared__ int sh[256];
    __shared__ int sb[256];
    int t = threadIdx.x;
    int bx = blockIdx.x;
    int i = bx * 256 + t;

    int v = 0;
    if (i < n) {
        v = g_degi[i];
        float d = 1.0f + (float)v;
        g_dis[i]  = rsqrtf(d);
        g_dinv[i] = 1.0f / d;
    }
    // block partial sum
    int s = v;
    #pragma unroll
    for (int off = 16; off; off >>= 1) s += __shfl_xor_sync(0xffffffffu, s, off);
    if ((t & 31) == 0) sh[t >> 5] = s;
    __syncthreads();
    if (t == 0) {
        int r = 0;
        #pragma unroll
        for (int w = 0; w < 8; w++) r += sh[w];
        g_bsum[bx] = r;
        __threadfence();
        atomicAdd(&g_scnt[0], 1);
    }
    // spin until all blocks have published
    if (t == 0) {
        while (atomicAdd(&g_scnt[0], 0) < nb) __nanosleep(32);
        __threadfence();
    }
    __syncthreads();

    // scan of block sums (redundant per block)
    int bv = (t < nb) ? g_bsum[t] : 0;
    sb[t] = bv;
    __syncthreads();
    #pragma unroll
    for (int off = 1; off < 256; off <<= 1) {
        int u = (t >= off) ? sb[t - off] : 0;
        __syncthreads();
        sb[t] += u;
        __syncthreads();
    }
    int bpre  = (bx > 0) ? sb[bx - 1] : 0;
    int total = sb[nb - 1];
    __syncthreads();

    // local scan of this block's degrees
    sh[t] = v;
    __syncthreads();
    #pragma unroll
    for (int off = 1; off < 256; off <<= 1) {
        int u = (t >= off) ? sh[t - off] : 0;
        __syncthreads();
        sh[t] += u;
        __syncthreads();
    }
    if (i < n) {
        int off = bpre + sh[t] - v;
        g_off[i] = off;
        g_cur[i] = off;
    }
    if (bx == nb - 1 && t == 0) g_off[n] = total;
}

// ---------------- phase 3: scatter ∥ wconv2 ∥ wgcn ----------------
__global__ void k_mid(const int* __restrict__ ei, const float* __restrict__ ipw,
                      const float* __restrict__ Ws, const float* __restrict__ Wf,
                      int E, int nsc, int nwc) {
    int t = threadIdx.x;
    int bx = blockIdx.x;
    if (bx < nsc) {
        int i = bx * 256 + t;
        if (i < E) {
            int s = ei[i];
            int d = ei[E + i];
            int pos = atomicAdd(&g_cur[d], 1);
            g_srcs[pos] = s;
        }
        return;
    }
    bx -= nsc;
    if (bx < nwc) {
        int i = bx * 256 + t;   // over 544*128 bf16-pairs
        if (i >= 544 * 128) return;
        int r = i / 128, p = i % 128;
        float a = 0.f, b = 0.f;
        if (r < 512) {
            a = ipw[r * 256 + 2 * p];
            b = ipw[r * 256 + 2 * p + 1];
        } else if (r < 520) {
            a = g_u[(r - 512) * 256 + 2 * p];
            b = g_u[(r - 512) * 256 + 2 * p + 1];
        } else if (r < 528) {
            float ua = g_u[(r - 520) * 256 + 2 * p];
            float ub = g_u[(r - 520) * 256 + 2 * p + 1];
            a = ua - __bfloat162float(__float2bfloat16(ua));
            b = ub - __bfloat162float(__float2bfloat16(ub));
        }
        *reinterpret_cast<uint32_t*>(&g_wb2[r * 256 + 2 * p]) = f2_to_bf2(a, b);
        return;
    }
    bx -= nwc;
    int i = bx * 256 + t;
    if (i >= 512 * 320) return;
    int nn = i / 320, k = i % 320;
    float v = 0.f;
    if (nn < 256) { if (k < 100) v = Ws[k * 256 + nn]; }
    else          { if (k >= 100 && k < 300) v = Wf[(k - 100) * 256 + (nn - 256)]; }
    g_wg[i] = __float2bfloat16(v);
}

// ---------------- phase 4: gather-aggregate + y epilogue (round-10 form) ----
__global__ __launch_bounds__(256) void k_gather(int n) {
    int w    = (blockIdx.x * blockDim.x + threadIdx.x) >> 5;
    int lane = threadIdx.x & 31;
    if (w >= n) return;
    int beg = g_off[w], end = g_off[w + 1];

    float acc0[8], acc1[8];
    #pragma unroll
    for (int j = 0; j < 8; j++) { acc0[j] = 0.f; acc1[j] = 0.f; }

    for (int base = beg; base < end; base += 32) {
        int cnt = min(32, end - base);
        int   s_l = 0;
        float w_l = 0.f;
        if (lane < cnt) {
            s_l = g_srcs[base + lane];
            w_l = g_dis[s_l];
        }
        for (int k = 0; k < cnt; k++) {
            int   s  = __shfl_sync(0xffffffffu, s_l, k);
            float wt = __shfl_sync(0xffffffffu, w_l, k);
            const uint4* xr = reinterpret_cast<const uint4*>(g_xb + (size_t)s * XB_PAD);
            uint4 v = __ldg(&xr[lane]);
            float2 f;
            f = bf2_to_f2(v.x); acc0[0] += wt * f.x; acc0[1] += wt * f.y;
            f = bf2_to_f2(v.y); acc0[2] += wt * f.x; acc0[3] += wt * f.y;
            f = bf2_to_f2(v.z); acc0[4] += wt * f.x; acc0[5] += wt * f.y;
            f = bf2_to_f2(v.w); acc0[6] += wt * f.x; acc0[7] += wt * f.y;
            if (lane < 6) {
                uint4 v2 = __ldg(&xr[32 + lane]);
                f = bf2_to_f2(v2.x); acc1[0] += wt * f.x; acc1[1] += wt * f.y;
                f = bf2_to_f2(v2.y); acc1[2] += wt * f.x; acc1[3] += wt * f.y;
                f = bf2_to_f2(v2.z); acc1[4] += wt * f.x; acc1[5] += wt * f.y;
                f = bf2_to_f2(v2.w); acc1[6] += wt * f.x; acc1[7] += wt * f.y;
            }
        }
    }

    float dw = g_dis[w], iw = g_dinv[w];
    const uint4* xr = reinterpret_cast<const uint4*>(g_xb + (size_t)w * XB_PAD);
    uint4* yr = reinterpret_cast<uint4*>(g_yb + (size_t)w * XB_PAD);
    {
        uint4 xs = xr[lane];
        float2 f0 = bf2_to_f2(xs.x), f1 = bf2_to_f2(xs.y);
        float2 f2 = bf2_to_f2(xs.z), f3 = bf2_to_f2(xs.w);
        uint4 st;
        st.x = f2_to_bf2(dw * acc0[0] + iw * f0.x, dw * acc0[1] + iw * f0.y);
        st.y = f2_to_bf2(dw * acc0[2] + iw * f1.x, dw * acc0[3] + iw * f1.y);
        st.z = f2_to_bf2(dw * acc0[4] + iw * f2.x, dw * acc0[5] + iw * f2.y);
        st.w = f2_to_bf2(dw * acc0[6] + iw * f3.x, dw * acc0[7] + iw * f3.y);
        yr[lane] = st;
    }
    if (lane < 6) {
        uint4 xs = xr[32 + lane];
        float2 f0 = bf2_to_f2(xs.x), f1 = bf2_to_f2(xs.y);
        float2 f2 = bf2_to_f2(xs.z), f3 = bf2_to_f2(xs.w);
        uint4 st;
        st.x = f2_to_bf2(dw * acc1[0] + iw * f0.x, dw * acc1[1] + iw * f0.y);
        st.y = f2_to_bf2(dw * acc1[2] + iw * f1.x, dw * acc1[3] + iw * f1.y);
        st.z = f2_to_bf2(dw * acc1[4] + iw * f2.x, dw * acc1[5] + iw * f2.y);
        st.w = f2_to_bf2(dw * acc1[6] + iw * f3.x, dw * acc1[7] + iw * f3.y);
        yr[32 + lane] = st;
    }
}

// ---------------- phase 5: FUSED tail: GCN GEMM blocks + attention blocks ----
#define GA_PAD 328
#define GB_ROWB 144
#define G_SM_A   0
#define G_SM_B0  41984
#define G_B_BYTES 73728
#define G_SM_B1  (G_SM_B0 + G_B_BYTES)
#define G_SM_BIAS (G_SM_B1 + G_B_BYTES)      // 189440
#define AT_PAD 264
#define AB_ROWB 144
#define OUT_PAD 552
#define A_SM_A   0
#define A_SM_B0  33792
#define A_B_BYTES 78336
#define A_SM_B1  (A_SM_B0 + A_B_BYTES)
#define A_SM_BIAS 190464
#define A_SM_RED  (A_SM_BIAS + 2176)
#define TAIL_SM_TOTAL 192704

__global__ __launch_bounds__(256, 1) void k_tail(
        const float* __restrict__ bsg, const float* __restrict__ bfg,
        const float* __restrict__ ipb, float* __restrict__ out,
        int n, int ngcn, int nattn) {
    extern __shared__ __align__(1024) unsigned char smraw[];
    int tid = threadIdx.x, wid = tid >> 5, lane = tid & 31;
    int bx = blockIdx.x;

    if (bx < ngcn) {
        // ================= GCN GEMM block =================
        __nv_bfloat16* A = reinterpret_cast<__nv_bfloat16*>(smraw + G_SM_A);
        float* sbias     = reinterpret_cast<float*>(smraw + G_SM_BIAS);
        int n0 = bx * 64;

        uint32_t b0_base = smem_u32(smraw + G_SM_B0);
        uint32_t b1_base = smem_u32(smraw + G_SM_B1);

        #pragma unroll
        for (int it = 0; it < 16; it++) {
            int i = it * 256 + tid;
            int rr = i >> 3, k4 = i & 7;
            cp16(b0_base + rr * GB_ROWB + k4 * 16, &g_wg[rr * 320 + 0 * 64 + k4 * 8]);
        }
        CP_COMMIT();
        #pragma unroll
        for (int it = 0; it < 16; it++) {
            int i = it * 256 + tid;
            int rr = i >> 3, k4 = i & 7;
            cp16(b1_base + rr * GB_ROWB + k4 * 16, &g_wg[rr * 320 + 1 * 64 + k4 * 8]);
        }
        CP_COMMIT();

        sbias[tid]       = bsg[tid];
        sbias[256 + tid] = bfg[tid];

        for (int i = tid; i < 64 * 40; i += 256) {
            int tok = i / 40, k4 = i % 40;
            int node = n0 + tok;
            uint4 v = make_uint4(0u, 0u, 0u, 0u);
            if (node < n && k4 < 38)
                v = *reinterpret_cast<const uint4*>(&g_yb[(size_t)node * XB_PAD + k4 * 8]);
            *reinterpret_cast<uint4*>(&A[tok * GA_PAD + k4 * 8]) = v;
        }

        uint32_t a_base = smem_u32(A);
        int mt = wid & 3;
        int nh = wid >> 2;

        float acc[32][4];
        #pragma unroll
        for (int j = 0; j < 32; j++)
            #pragma unroll
            for (int r = 0; r < 4; r++) acc[j][r] = 0.f;

        int a_row  = mt * 16 + (lane & 15);
        int a_col8 = (lane >> 4) * 8;
        int b_rofs = (lane & 7) + (lane >> 4) * 8;
        int b_col8 = ((lane >> 3) & 1) * 8;

        for (int c = 0; c < 5; c++) {
            if (c < 4) CP_WAIT(1); else CP_WAIT(0);
            __syncthreads();
            uint32_t b_base = (c & 1) ? b1_base : b0_base;

            #pragma unroll
            for (int ks = 0; ks < 4; ks++) {
                uint32_t af[4];
                uint32_t aaddr = a_base +
                    (uint32_t)(a_row * GA_PAD + c * 64 + ks * 16 + a_col8) * 2;
                ldsm4(af[0], af[1], af[2], af[3], aaddr);
                #pragma unroll
                for (int j = 0; j < 16; j++) {
                    int nrow = nh * 256 + j * 16 + b_rofs;
                    uint32_t baddr = b_base + nrow * GB_ROWB + ks * 32 + b_col8 * 2;
                    uint32_t b0, b1, b2, b3;
                    ldsm4(b0, b1, b2, b3, baddr);
                    mma16816(acc[2 * j],     af, b0, b1);
                    mma16816(acc[2 * j + 1], af, b2, b3);
                }
            }
            if (c + 2 < 5) {
                __syncthreads();
                uint32_t dstb = (c & 1) ? b1_base : b0_base;
                #pragma unroll
                for (int it = 0; it < 16; it++) {
                    int i = it * 256 + tid;
                    int rr = i >> 3, k4 = i & 7;
                    cp16(dstb + rr * GB_ROWB + k4 * 16,
                         &g_wg[rr * 320 + (c + 2) * 64 + k4 * 8]);
                }
                CP_COMMIT();
            }
        }

        int r0 = mt * 16 + (lane >> 2);
        int node0 = n0 + r0, node1 = node0 + 8;
        int cofs = (lane & 3) * 2;
        #pragma unroll
        for (int j = 0; j < 32; j++) {
            int col = nh * 256 + j * 8 + cofs;
            float b0 = sbias[col], b1 = sbias[col + 1];
            if (node0 < n) {
                uint32_t p = f2_to_bf2(fmaxf(acc[j][0] + b0, 0.f),
                                       fmaxf(acc[j][1] + b1, 0.f));
                *reinterpret_cast<uint32_t*>(&g_sfb[(size_t)node0 * 512 + col]) = p;
            }
            if (node1 < n) {
                uint32_t p = f2_to_bf2(fmaxf(acc[j][2] + b0, 0.f),
                                       fmaxf(acc[j][3] + b1, 0.f));
                *reinterpret_cast<uint32_t*>(&g_sfb[(size_t)node1 * 512 + col]) = p;
            }
        }

        __syncthreads();
        if (tid == 0) {
            __threadfence();
            atomicExch(&g_flag[bx], 1);
        }
        return;
    }

    // ================= attention block =================
    {
        int ai = bx - ngcn;
        __nv_bfloat16* A = reinterpret_cast<__nv_bfloat16*>(smraw + A_SM_A);
        float* Out   = reinterpret_cast<float*>(smraw + A_SM_B0);
        float* sbias = reinterpret_cast<float*>(smraw + A_SM_BIAS);
        float* red   = reinterpret_cast<float*>(smraw + A_SM_RED);
        int n0 = ai * 32;

        uint32_t b0_base = smem_u32(smraw + A_SM_B0);
        uint32_t b1_base = smem_u32(smraw + A_SM_B1);

        #pragma unroll
        for (int it = 0; it < 17; it++) {
            int i = it * 256 + tid;
            int rr = i >> 3, k4 = i & 7;
            cp16(b0_base + rr * AB_ROWB + k4 * 16, &g_wb2[rr * 256 + 0 * 64 + k4 * 8]);
        }
        CP_COMMIT();
        #pragma unroll
        for (int it = 0; it < 17; it++) {
            int i = it * 256 + tid;
            int rr = i >> 3, k4 = i & 7;
            cp16(b1_base + rr * AB_ROWB + k4 * 16, &g_wb2[rr * 256 + 1 * 64 + k4 * 8]);
        }
        CP_COMMIT();

        for (int i = tid; i < 544; i += 256) {
            float v = 0.f;
            if (i < 512) v = ipb[i];
            else if (i < 520) v = g_c[i - 512];
            sbias[i] = v;
        }

        if (tid == 0) {
            while (atomicAdd(&g_flag[ai >> 1], 0) == 0) __nanosleep(64);
            __threadfence();
        }
        __syncthreads();

        #pragma unroll
        for (int it = 0; it < 16; it++) {
            int i = it * 256 + tid;
            int tok = i >> 6, k4 = i & 63;
            int node = n0 + (tok >> 1);
            unsigned long long v = 0ull;
            if (node < n)
                v = *reinterpret_cast<const unsigned long long*>(
                        &g_sfb[(size_t)node * 512 + (tok & 1) * 256 + k4 * 4]);
            *reinterpret_cast<unsigned long long*>(&A[tok * AT_PAD + k4 * 4]) = v;
        }

        uint32_t a_base = smem_u32(A);
        int mt = wid & 3;
        int nh = wid >> 2;

        float acc[34][4];
        #pragma unroll
        for (int j = 0; j < 34; j++)
            #pragma unroll
            for (int r = 0; r < 4; r++) acc[j][r] = 0.f;

        int a_row = mt * 16 + (lane & 15);
        int a_col8 = (lane >> 4) * 8;
        int b_rofs = (lane & 7) + (lane >> 4) * 8;
        int b_col8 = ((lane >> 3) & 1) * 8;

        for (int c = 0; c < 4; c++) {
            if (c < 3) CP_WAIT(1); else CP_WAIT(0);
            __syncthreads();
            uint32_t b_base = (c & 1) ? b1_base : b0_base;

            #pragma unroll
            for (int ks = 0; ks < 4; ks++) {
                uint32_t af[4];
                uint32_t aaddr = a_base +
                    (uint32_t)(a_row * AT_PAD + c * 64 + ks * 16 + a_col8) * 2;
                ldsm4(af[0], af[1], af[2], af[3], aaddr);
                #pragma unroll
                for (int j = 0; j < 17; j++) {
                    int nrow = nh * 272 + j * 16 + b_rofs;
                    uint32_t baddr = b_base + nrow * AB_ROWB + ks * 32 + b_col8 * 2;
                    uint32_t b0, b1, b2, b3;
                    ldsm4(b0, b1, b2, b3, baddr);
                    mma16816(acc[2 * j],     af, b0, b1);
                    mma16816(acc[2 * j + 1], af, b2, b3);
                }
            }
            if (c + 2 < 4) {
                __syncthreads();
                uint32_t dstb = (c & 1) ? b1_base : b0_base;
                #pragma unroll
                for (int it = 0; it < 17; it++) {
                    int i = it * 256 + tid;
                    int rr = i >> 3, k4 = i & 7;
                    cp16(dstb + rr * AB_ROWB + k4 * 16,
                         &g_wb2[rr * 256 + (c + 2) * 64 + k4 * 8]);
                }
                CP_COMMIT();
            }
        }
        __syncthreads();

        {
            int row0 = mt * 16 + (lane >> 2);
            int cofs = (lane & 3) * 2;
            #pragma unroll
            for (int j = 0; j < 34; j++) {
                int col = nh * 272 + j * 8 + cofs;
                float bb0 = sbias[col], bb1 = sbias[col + 1];
                Out[row0 * OUT_PAD + col]           = acc[j][0] + bb0;
                Out[row0 * OUT_PAD + col + 1]       = acc[j][1] + bb1;
                Out[(row0 + 8) * OUT_PAD + col]     = acc[j][2] + bb0;
                Out[(row0 + 8) * OUT_PAD + col + 1] = acc[j][3] + bb1;
            }
        }
        __syncthreads();

        int node = tid >> 3, h = tid & 7;
        const float4* q0 = reinterpret_cast<const float4*>(
            &Out[(node * 2 + 0) * OUT_PAD + h * 32]);
        const float4* q1 = reinterpret_cast<const float4*>(
            &Out[(node * 2 + 1) * OUT_PAD + h * 32]);
        const float4* k0 = reinterpret_cast<const float4*>(
            &Out[(node * 2 + 0) * OUT_PAD + 256 + h * 32]);
        const float4* k1 = reinterpret_cast<const float4*>(
            &Out[(node * 2 + 1) * OUT_PAD + 256 + h * 32]);
        float s00 = 0.f, s01 = 0.f, s10 = 0.f, s11 = 0.f;
        #pragma unroll
        for (int d = 0; d < 8; d++) {
            float4 a0 = q0[d], a1 = q1[d], b0 = k0[d], b1 = k1[d];
            s00 += a0.x * b0.x + a0.y * b0.y + a0.z * b0.z + a0.w * b0.w;
            s01 += a0.x * b1.x + a0.y * b1.y + a0.z * b1.z + a0.w * b1.w;
            s10 += a1.x * b0.x + a1.y * b0.y + a1.z * b0.z + a1.w * b0.w;
            s11 += a1.x * b1.x + a1.y * b1.y + a1.z * b1.z + a1.w * b1.w;
        }
        const float scale = 0.17677669529663687f;
        s00 *= scale; s01 *= scale; s10 *= scale; s11 *= scale;
        float m0 = fmaxf(s00, s01), m1 = fmaxf(s10, s11);
        float e00 = expf(s00 - m0), e01 = expf(s01 - m0);
        float e10 = expf(s10 - m1), e11 = expf(s11 - m1);
        float d0 = e00 + e01, d1 = e10 + e11;
        float a00 = e00 / d0, a01 = e01 / d0;
        float a10 = e10 / d1, a11 = e11 / d1;
        float dv0 = Out[(node * 2 + 0) * OUT_PAD + 512 + h]
                  + Out[(node * 2 + 0) * OUT_PAD + 520 + h];
        float dv1 = Out[(node * 2 + 1) * OUT_PAD + 512 + h]
                  + Out[(node * 2 + 1) * OUT_PAD + 520 + h];
        float contrib = 0.5f * ((a00 + a10) * dv0 + (a01 + a11) * dv1);
        if (n0 + node >= n) contrib = 0.f;

        #pragma unroll
        for (int off = 16; off; off >>= 1)
            contrib += __shfl_xor_sync(0xffffffffu, contrib, off);
        if (lane == 0) red[wid] = contrib;
        __syncthreads();
        if (tid == 0) {
            float s = 0.f;
            #pragma unroll
            for (int w = 0; w < 8; w++) s += red[w];
            atomicAdd(&g_acc[0], s);
            __threadfence();
            int done = atomicAdd(&g_done[0], 1);
            if (done == nattn - 1) {
                out[0] = g_acc[0] / (float)n + g_konst[0];
            }
        }
    }
}

// ---------------- launch ----------------
extern "C" void kernel_launch(void* const* d_in, const int* in_sizes, int n_in,
                              void* d_out, int out_size) {
    const float* x   = (const float*)d_in[0];
    const int*   ei  = (const int*)d_in[1];
    const float* W_s = (const float*)d_in[2];
    const float* b_s = (const float*)d_in[3];
    const float* W_f = (const float*)d_in[4];
    const float* b_f = (const float*)d_in[5];
    const float* ipw = (const float*)d_in[6];
    const float* ipb = (const float*)d_in[7];
    const float* opw = (const float*)d_in[8];
    const float* opb = (const float*)d_in[9];
    const float* ow  = (const float*)d_in[10];
    const float* ob  = (const float*)d_in[11];

    int n = in_sizes[0] / FEAT;
    int E = in_sizes[1] / 2;
    int nb  = (n + 255) / 256;             // scan blocks
    int ndeg = (E + 255) / 256;            // degree/scatter blocks
    int nxc  = (n * 152 + 255) / 256;      // xconv blocks
    int nwc  = (544 * 128 + 255) / 256;    // wconv2 blocks
    int nwg  = (512 * 320 + 255) / 256;    // wgcn blocks
    int ngcn  = (n + 63) / 64;
    int nattn = (n + 31) / 32;

    k_init <<<nb + 1, 256>>>(ipw, ipb, opw, opb, ow, ob, n, nb);
    k_front<<<ndeg + nxc, 256>>>(ei, x, E, n, ndeg);
    k_scan <<<nb, 256>>>(nb, n);
    k_mid  <<<ndeg + nwc + nwg, 256>>>(ei, ipw, W_s, W_f, E, ndeg, nwc);
    k_gather<<<(n + 7) / 8, 256>>>(n);

    cudaFuncSetAttribute(k_tail, cudaFuncAttributeMaxDynamicSharedMemorySize, TAIL_SM_TOTAL);
    k_tail<<<ngcn + nattn, 256, TAIL_SM_TOTAL>>>(b_s, b_f, ipb, (float*)d_out,
                                                 n, ngcn, nattn);
}

// round 17
// speedup vs baseline: 1.0242x; 1.0242x over previous
#include <cuda_runtime.h>
#include <cuda_bf16.h>
#include <cstdint>

#define N_NODES_MAX 50000
#define E_MAX 1600000
#define FEAT 300
#define XB_PAD 304              // padded bf16 row (38 uint4)
#define HID 256
#define NFLAG_MAX ((N_NODES_MAX + 63) / 64)

// ---------------- device scratch ----------------
__device__ int   g_degi[N_NODES_MAX];
__device__ int   g_off [N_NODES_MAX + 1];
__device__ int   g_cur [N_NODES_MAX];
__device__ int   g_srcs[E_MAX];
__device__ int   g_bsum[256];
__device__ int   g_done[1];
__device__ int   g_flag[NFLAG_MAX];
__device__ __align__(16) float g_dis [N_NODES_MAX];
__device__ __align__(16) float g_dinv[N_NODES_MAX];
__device__ __align__(16) __nv_bfloat16 g_xb [N_NODES_MAX * XB_PAD];  // x bf16 padded
__device__ __align__(16) __nv_bfloat16 g_yb [N_NODES_MAX * XB_PAD];  // y = dis*agg+dinv*x
__device__ __align__(16) __nv_bfloat16 g_sfb[N_NODES_MAX * 2 * HID]; // comb bf16
__device__ __align__(16) __nv_bfloat16 g_wb2[544 * 256];             // QK weights + u_hi + u_lo
__device__ __align__(16) __nv_bfloat16 g_wg [512 * 320];             // block-diag GCN W bf16
__device__ __align__(16) float g_u   [8 * 256];
__device__ __align__(16) float g_c   [8];
__device__ float g_konst[1];
__device__ float g_acc [1];

// ---------------- helpers ----------------
__device__ __forceinline__ float2 bf2_to_f2(uint32_t u) {
    float2 r;
    r.x = __uint_as_float(u << 16);
    r.y = __uint_as_float(u & 0xffff0000u);
    return r;
}
__device__ __forceinline__ uint32_t f2_to_bf2(float a, float b) {
    __nv_bfloat162 p = __float22bfloat162_rn(make_float2(a, b));
    return *reinterpret_cast<uint32_t*>(&p);
}
__device__ __forceinline__ uint32_t smem_u32(const void* p) {
    uint32_t a;
    asm("{ .reg .u64 t; cvta.to.shared.u64 t, %1; cvt.u32.u64 %0, t; }"
        : "=r"(a) : "l"(p));
    return a;
}
__device__ __forceinline__ void ldsm4(uint32_t& r0, uint32_t& r1,
                                      uint32_t& r2, uint32_t& r3, uint32_t addr) {
    asm volatile("ldmatrix.sync.aligned.m8n8.x4.shared.b16 {%0,%1,%2,%3}, [%4];"
                 : "=r"(r0), "=r"(r1), "=r"(r2), "=r"(r3) : "r"(addr));
}
__device__ __forceinline__ void mma16816(float* d, const uint32_t* a,
                                         uint32_t b0, uint32_t b1) {
    asm volatile(
        "mma.sync.aligned.m16n8k16.row.col.f32.bf16.bf16.f32 "
        "{%0,%1,%2,%3}, {%4,%5,%6,%7}, {%8,%9}, {%0,%1,%2,%3};"
        : "+f"(d[0]), "+f"(d[1]), "+f"(d[2]), "+f"(d[3])
        : "r"(a[0]), "r"(a[1]), "r"(a[2]), "r"(a[3]), "r"(b0), "r"(b1));
}
__device__ __forceinline__ void cp16(uint32_t smem_dst, const void* gsrc) {
    asm volatile("cp.async.cg.shared.global [%0], [%1], 16;"
                 :: "r"(smem_dst), "l"(gsrc) : "memory");
}
#define CP_COMMIT() asm volatile("cp.async.commit_group;" ::: "memory")
#define CP_WAIT(N)  asm volatile("cp.async.wait_group %0;" :: "n"(N) : "memory")

// ---------------- phase 0: zero ∥ prep  (block-range fusion) ----------------
__global__ void k_init(const float* __restrict__ ipw, const float* __restrict__ ipb,
                       const float* __restrict__ opw, const float* __restrict__ opb,
                       const float* __restrict__ ow,  const float* __restrict__ ob,
                       int n, int nzb) {
    int t = threadIdx.x;
    if ((int)blockIdx.x < nzb) {
        int i = blockIdx.x * 256 + t;
        if (i < n) g_degi[i] = 0;
        if (i < NFLAG_MAX) g_flag[i] = 0;
        if (i == 0) { g_acc[0] = 0.f; g_done[0] = 0; }
        return;
    }
    // ---- prep (single block) ----
    __shared__ float vout[256];
    float acc = 0.f;
    for (int j = 0; j < 256; j++) acc += opw[j * 256 + t] * ow[j];
    vout[t] = acc;
    __syncthreads();
    #pragma unroll
    for (int h = 0; h < 8; h++) {
        float a = 0.f;
        #pragma unroll 8
        for (int d = 0; d < 32; d++)
            a += ipw[(512 + h * 32 + d) * 256 + t] * vout[h * 32 + d];
        g_u[h * 256 + t] = a;
    }
    if (t < 8) {
        float c = 0.f;
        for (int d = 0; d < 32; d++) c += ipb[512 + t * 32 + d] * vout[t * 32 + d];
        g_c[t] = c;
    }
    if (t == 0) {
        float c = 0.f;
        for (int j = 0; j < 256; j++) c += opb[j] * ow[j];
        g_konst[0] = c + ob[0];
    }
}

// ---------------- phase 1: deg ∥ xconv ----------------
__global__ void k_front(const int* __restrict__ ei, const float* __restrict__ x,
                        int E, int n, int ndeg) {
    int t = threadIdx.x;
    if ((int)blockIdx.x < ndeg) {
        int i = blockIdx.x * 256 + t;
        if (i < E) atomicAdd(&g_degi[ei[E + i]], 1);
        return;
    }
    int j = (blockIdx.x - ndeg) * 256 + t;
    if (j >= n * 152) return;
    int row = j / 152, p = j % 152;
    uint32_t v = 0;
    if (p < 150) {
        float2 f = *reinterpret_cast<const float2*>(&x[row * FEAT + 2 * p]);
        v = f2_to_bf2(f.x, f.y);
    }
    *reinterpret_cast<uint32_t*>(&g_xb[row * XB_PAD + 2 * p]) = v;
}

// ---------------- phase 2a: per-block sums + normalizers ----------------
__global__ void k_scanA(int n) {
    __shared__ int sh[8];
    int i = blockIdx.x * 256 + threadIdx.x;
    int v = 0;
    if (i < n) {
        v = g_degi[i];
        float d = 1.0f + (float)v;
        g_dis[i]  = rsqrtf(d);
        g_dinv[i] = 1.0f / d;
    }
    int s = v;
    #pragma unroll
    for (int off = 16; off; off >>= 1) s += __shfl_xor_sync(0xffffffffu, s, off);
    if ((threadIdx.x & 31) == 0) sh[threadIdx.x >> 5] = s;
    __syncthreads();
    if (threadIdx.x == 0) {
        int r = 0;
        #pragma unroll
        for (int w = 0; w < 8; w++) r += sh[w];
        g_bsum[blockIdx.x] = r;
    }
}

// ---------------- phase 2b: offsets (each block re-scans bsum locally) ------
__global__ void k_scanC(int nb, int n) {
    __shared__ int sb[256];
    __shared__ int sh[256];
    int t = threadIdx.x;
    int bx = blockIdx.x;

    int bv = (t < nb) ? g_bsum[t] : 0;
    sb[t] = bv;
    __syncthreads();
    #pragma unroll
    for (int off = 1; off < 256; off <<= 1) {
        int u = (t >= off) ? sb[t - off] : 0;
        __syncthreads();
        sb[t] += u;
        __syncthreads();
    }
    int bpre  = (bx > 0) ? sb[bx - 1] : 0;
    int total = sb[nb - 1];
    __syncthreads();

    int i = bx * 256 + t;
    int v = (i < n) ? g_degi[i] : 0;
    sh[t] = v;
    __syncthreads();
    #pragma unroll
    for (int off = 1; off < 256; off <<= 1) {
        int u = (t >= off) ? sh[t - off] : 0;
        __syncthreads();
        sh[t] += u;
        __syncthreads();
    }
    if (i < n) {
        int off = bpre + sh[t] - v;
        g_off[i] = off;
        g_cur[i] = off;
    }
    if (bx == nb - 1 && t == 0) g_off[n] = total;
}

// ---------------- phase 3: scatter ∥ wconv2 ∥ wgcn ----------------
__global__ void k_mid(const int* __restrict__ ei, const float* __restrict__ ipw,
                      const float* __restrict__ Ws, const float* __restrict__ Wf,
                      int E, int nsc, int nwc) {
    int t = threadIdx.x;
    int bx = blockIdx.x;
    if (bx < nsc) {
        int i = bx * 256 + t;
        if (i < E) {
            int s = ei[i];
            int d = ei[E + i];
            int pos = atomicAdd(&g_cur[d], 1);
            g_srcs[pos] = s;
        }
        return;
    }
    bx -= nsc;
    if (bx < nwc) {
        int i = bx * 256 + t;   // over 544*128 bf16-pairs
        if (i >= 544 * 128) return;
        int r = i / 128, p = i % 128;
        float a = 0.f, b = 0.f;
        if (r < 512) {
            a = ipw[r * 256 + 2 * p];
            b = ipw[r * 256 + 2 * p + 1];
        } else if (r < 520) {
            a = g_u[(r - 512) * 256 + 2 * p];
            b = g_u[(r - 512) * 256 + 2 * p + 1];
        } else if (r < 528) {
            float ua = g_u[(r - 520) * 256 + 2 * p];
            float ub = g_u[(r - 520) * 256 + 2 * p + 1];
            a = ua - __bfloat162float(__float2bfloat16(ua));
            b = ub - __bfloat162float(__float2bfloat16(ub));
        }
        *reinterpret_cast<uint32_t*>(&g_wb2[r * 256 + 2 * p]) = f2_to_bf2(a, b);
        return;
    }
    bx -= nwc;
    int i = bx * 256 + t;
    if (i >= 512 * 320) return;
    int nn = i / 320, k = i % 320;
    float v = 0.f;
    if (nn < 256) { if (k < 100) v = Ws[k * 256 + nn]; }
    else          { if (k >= 100 && k < 300) v = Wf[(k - 100) * 256 + (nn - 256)]; }
    g_wg[i] = __float2bfloat16(v);
}

// ---------------- phase 4: gather-aggregate + y epilogue ----------------
__global__ __launch_bounds__(256) void k_gather(int n) {
    int w    = (blockIdx.x * blockDim.x + threadIdx.x) >> 5;
    int lane = threadIdx.x & 31;
    if (w >= n) return;
    int beg = g_off[w], end = g_off[w + 1];

    float acc0[8], acc1[8];
    #pragma unroll
    for (int j = 0; j < 8; j++) { acc0[j] = 0.f; acc1[j] = 0.f; }

    for (int base = beg; base < end; base += 32) {
        int cnt = min(32, end - base);
        int   s_l = 0;
        float w_l = 0.f;
        if (lane < cnt) {
            s_l = g_srcs[base + lane];
            w_l = g_dis[s_l];
        }
        for (int k = 0; k < cnt; k++) {
            int   s  = __shfl_sync(0xffffffffu, s_l, k);
            float wt = __shfl_sync(0xffffffffu, w_l, k);
            const uint4* xr = reinterpret_cast<const uint4*>(g_xb + (size_t)s * XB_PAD);
            uint4 v = __ldg(&xr[lane]);
            float2 f;
            f = bf2_to_f2(v.x); acc0[0] += wt * f.x; acc0[1] += wt * f.y;
            f = bf2_to_f2(v.y); acc0[2] += wt * f.x; acc0[3] += wt * f.y;
            f = bf2_to_f2(v.z); acc0[4] += wt * f.x; acc0[5] += wt * f.y;
            f = bf2_to_f2(v.w); acc0[6] += wt * f.x; acc0[7] += wt * f.y;
            if (lane < 6) {
                uint4 v2 = __ldg(&xr[32 + lane]);
                f = bf2_to_f2(v2.x); acc1[0] += wt * f.x; acc1[1] += wt * f.y;
                f = bf2_to_f2(v2.y); acc1[2] += wt * f.x; acc1[3] += wt * f.y;
                f = bf2_to_f2(v2.z); acc1[4] += wt * f.x; acc1[5] += wt * f.y;
                f = bf2_to_f2(v2.w); acc1[6] += wt * f.x; acc1[7] += wt * f.y;
            }
        }
    }

    float dw = g_dis[w], iw = g_dinv[w];
    const uint4* xr = reinterpret_cast<const uint4*>(g_xb + (size_t)w * XB_PAD);
    uint4* yr = reinterpret_cast<uint4*>(g_yb + (size_t)w * XB_PAD);
    {
        uint4 xs = xr[lane];
        float2 f0 = bf2_to_f2(xs.x), f1 = bf2_to_f2(xs.y);
        float2 f2 = bf2_to_f2(xs.z), f3 = bf2_to_f2(xs.w);
        uint4 st;
        st.x = f2_to_bf2(dw * acc0[0] + iw * f0.x, dw * acc0[1] + iw * f0.y);
        st.y = f2_to_bf2(dw * acc0[2] + iw * f1.x, dw * acc0[3] + iw * f1.y);
        st.z = f2_to_bf2(dw * acc0[4] + iw * f2.x, dw * acc0[5] + iw * f2.y);
        st.w = f2_to_bf2(dw * acc0[6] + iw * f3.x, dw * acc0[7] + iw * f3.y);
        yr[lane] = st;
    }
    if (lane < 6) {
        uint4 xs = xr[32 + lane];
        float2 f0 = bf2_to_f2(xs.x), f1 = bf2_to_f2(xs.y);
        float2 f2 = bf2_to_f2(xs.z), f3 = bf2_to_f2(xs.w);
        uint4 st;
        st.x = f2_to_bf2(dw * acc1[0] + iw * f0.x, dw * acc1[1] + iw * f0.y);
        st.y = f2_to_bf2(dw * acc1[2] + iw * f1.x, dw * acc1[3] + iw * f1.y);
        st.z = f2_to_bf2(dw * acc1[4] + iw * f2.x, dw * acc1[5] + iw * f2.y);
        st.w = f2_to_bf2(dw * acc1[6] + iw * f3.x, dw * acc1[7] + iw * f3.y);
        yr[32 + lane] = st;
    }
}

// ---------------- phase 5: FUSED tail: GCN GEMM blocks + attention blocks ----
#define GA_PAD 328
#define GB_ROWB 144
#define G_SM_A   0
#define G_SM_B0  41984
#define G_B_BYTES 73728
#define G_SM_B1  (G_SM_B0 + G_B_BYTES)
#define G_SM_BIAS (G_SM_B1 + G_B_BYTES)      // 189440
#define AT_PAD 264
#define AB_ROWB 144
#define OUT_PAD 552
#define A_SM_A   0
#define A_SM_B0  33792
#define A_B_BYTES 78336
#define A_SM_B1  (A_SM_B0 + A_B_BYTES)
#define A_SM_BIAS 190464
#define A_SM_RED  (A_SM_BIAS + 2176)
#define TAIL_SM_TOTAL 192704

__global__ __launch_bounds__(256, 1) void k_tail(
        const float* __restrict__ bsg, const float* __restrict__ bfg,
        const float* __restrict__ ipb, float* __restrict__ out,
        int n, int ngcn, int nattn) {
    extern __shared__ __align__(1024) unsigned char smraw[];
    int tid = threadIdx.x, wid = tid >> 5, lane = tid & 31;
    int bx = blockIdx.x;

    if (bx < ngcn) {
        // ================= GCN GEMM block =================
        __nv_bfloat16* A = reinterpret_cast<__nv_bfloat16*>(smraw + G_SM_A);
        float* sbias     = reinterpret_cast<float*>(smraw + G_SM_BIAS);
        int n0 = bx * 64;

        uint32_t b0_base = smem_u32(smraw + G_SM_B0);
        uint32_t b1_base = smem_u32(smraw + G_SM_B1);

        #pragma unroll
        for (int it = 0; it < 16; it++) {
            int i = it * 256 + tid;
            int rr = i >> 3, k4 = i & 7;
            cp16(b0_base + rr * GB_ROWB + k4 * 16, &g_wg[rr * 320 + 0 * 64 + k4 * 8]);
        }
        CP_COMMIT();
        #pragma unroll
        for (int it = 0; it < 16; it++) {
            int i = it * 256 + tid;
            int rr = i >> 3, k4 = i & 7;
            cp16(b1_base + rr * GB_ROWB + k4 * 16, &g_wg[rr * 320 + 1 * 64 + k4 * 8]);
        }
        CP_COMMIT();

        sbias[tid]       = bsg[tid];
        sbias[256 + tid] = bfg[tid];

        for (int i = tid; i < 64 * 40; i += 256) {
            int tok = i / 40, k4 = i % 40;
            int node = n0 + tok;
            uint4 v = make_uint4(0u, 0u, 0u, 0u);
            if (node < n && k4 < 38)
                v = *reinterpret_cast<const uint4*>(&g_yb[(size_t)node * XB_PAD + k4 * 8]);
            *reinterpret_cast<uint4*>(&A[tok * GA_PAD + k4 * 8]) = v;
        }

        uint32_t a_base = smem_u32(A);
        int mt = wid & 3;
        int nh = wid >> 2;

        float acc[32][4];
        #pragma unroll
        for (int j = 0; j < 32; j++)
            #pragma unroll
            for (int r = 0; r < 4; r++) acc[j][r] = 0.f;

        int a_row  = mt * 16 + (lane & 15);
        int a_col8 = (lane >> 4) * 8;
        int b_rofs = (lane & 7) + (lane >> 4) * 8;
        int b_col8 = ((lane >> 3) & 1) * 8;

        for (int c = 0; c < 5; c++) {
            if (c < 4) CP_WAIT(1); else CP_WAIT(0);
            __syncthreads();
            uint32_t b_base = (c & 1) ? b1_base : b0_base;

            #pragma unroll
            for (int ks = 0; ks < 4; ks++) {
                uint32_t af[4];
                uint32_t aaddr = a_base +
                    (uint32_t)(a_row * GA_PAD + c * 64 + ks * 16 + a_col8) * 2;
                ldsm4(af[0], af[1], af[2], af[3], aaddr);
                #pragma unroll
                for (int j = 0; j < 16; j++) {
                    int nrow = nh * 256 + j * 16 + b_rofs;
                    uint32_t baddr = b_base + nrow * GB_ROWB + ks * 32 + b_col8 * 2;
                    uint32_t b0, b1, b2, b3;
                    ldsm4(b0, b1, b2, b3, baddr);
                    mma16816(acc[2 * j],     af, b0, b1);
                    mma16816(acc[2 * j + 1], af, b2, b3);
                }
            }
            if (c + 2 < 5) {
                __syncthreads();
                uint32_t dstb = (c & 1) ? b1_base : b0_base;
                #pragma unroll
                for (int it = 0; it < 16; it++) {
                    int i = it * 256 + tid;
                    int rr = i >> 3, k4 = i & 7;
                    cp16(dstb + rr * GB_ROWB + k4 * 16,
                         &g_wg[rr * 320 + (c + 2) * 64 + k4 * 8]);
                }
                CP_COMMIT();
            }
        }

        int r0 = mt * 16 + (lane >> 2);
        int node0 = n0 + r0, node1 = node0 + 8;
        int cofs = (lane & 3) * 2;
        #pragma unroll
        for (int j = 0; j < 32; j++) {
            int col = nh * 256 + j * 8 + cofs;
            float b0 = sbias[col], b1 = sbias[col + 1];
            if (node0 < n) {
                uint32_t p = f2_to_bf2(fmaxf(acc[j][0] + b0, 0.f),
                                       fmaxf(acc[j][1] + b1, 0.f));
                *reinterpret_cast<uint32_t*>(&g_sfb[(size_t)node0 * 512 + col]) = p;
            }
            if (node1 < n) {
                uint32_t p = f2_to_bf2(fmaxf(acc[j][2] + b0, 0.f),
                                       fmaxf(acc[j][3] + b1, 0.f));
                *reinterpret_cast<uint32_t*>(&g_sfb[(size_t)node1 * 512 + col]) = p;
            }
        }

        __syncthreads();
        if (tid == 0) {
            __threadfence();
            atomicExch(&g_flag[bx], 1);
        }
        return;
    }

    // ================= attention block =================
    {
        int ai = bx - ngcn;
        __nv_bfloat16* A = reinterpret_cast<__nv_bfloat16*>(smraw + A_SM_A);
        float* Out   = reinterpret_cast<float*>(smraw + A_SM_B0);
        float* sbias = reinterpret_cast<float*>(smraw + A_SM_BIAS);
        float* red   = reinterpret_cast<float*>(smraw + A_SM_RED);
        int n0 = ai * 32;

        uint32_t b0_base = smem_u32(smraw + A_SM_B0);
        uint32_t b1_base = smem_u32(smraw + A_SM_B1);

        #pragma unroll
        for (int it = 0; it < 17; it++) {
            int i = it * 256 + tid;
            int rr = i >> 3, k4 = i & 7;
            cp16(b0_base + rr * AB_ROWB + k4 * 16, &g_wb2[rr * 256 + 0 * 64 + k4 * 8]);
        }
        CP_COMMIT();
        #pragma unroll
        for (int it = 0; it < 17; it++) {
            int i = it * 256 + tid;
            int rr = i >> 3, k4 = i & 7;
            cp16(b1_base + rr * AB_ROWB + k4 * 16, &g_wb2[rr * 256 + 1 * 64 + k4 * 8]);
        }
        CP_COMMIT();

        for (int i = tid; i < 544; i += 256) {
            float v = 0.f;
            if (i < 512) v = ipb[i];
            else if (i < 520) v = g_c[i - 512];
            sbias[i] = v;
        }

        if (tid == 0) {
            while (atomicAdd(&g_flag[ai >> 1], 0) == 0) __nanosleep(64);
            __threadfence();
        }
        __syncthreads();

        #pragma unroll
        for (int it = 0; it < 16; it++) {
            int i = it * 256 + tid;
            int tok = i >> 6, k4 = i & 63;
            int node = n0 + (tok >> 1);
            unsigned long long v = 0ull;
            if (node < n)
                v = *reinterpret_cast<const unsigned long long*>(
                        &g_sfb[(size_t)node * 512 + (tok & 1) * 256 + k4 * 4]);
            *reinterpret_cast<unsigned long long*>(&A[tok * AT_PAD + k4 * 4]) = v;
        }

        uint32_t a_base = smem_u32(A);
        int mt = wid & 3;
        int nh = wid >> 2;

        float acc[34][4];
        #pragma unroll
        for (int j = 0; j < 34; j++)
            #pragma unroll
            for (int r = 0; r < 4; r++) acc[j][r] = 0.f;

        int a_row = mt * 16 + (lane & 15);
        int a_col8 = (lane >> 4) * 8;
        int b_rofs = (lane & 7) + (lane >> 4) * 8;
        int b_col8 = ((lane >> 3) & 1) * 8;

        for (int c = 0; c < 4; c++) {
            if (c < 3) CP_WAIT(1); else CP_WAIT(0);
            __syncthreads();
            uint32_t b_base = (c & 1) ? b1_base : b0_base;

            #pragma unroll
            for (int ks = 0; ks < 4; ks++) {
                uint32_t af[4];
                uint32_t aaddr = a_base +
                    (uint32_t)(a_row * AT_PAD + c * 64 + ks * 16 + a_col8) * 2;
                ldsm4(af[0], af[1], af[2], af[3], aaddr);
                #pragma unroll
                for (int j = 0; j < 17; j++) {
                    int nrow = nh * 272 + j * 16 + b_rofs;
                    uint32_t baddr = b_base + nrow * AB_ROWB + ks * 32 + b_col8 * 2;
                    uint32_t b0, b1, b2, b3;
                    ldsm4(b0, b1, b2, b3, baddr);
                    mma16816(acc[2 * j],     af, b0, b1);
                    mma16816(acc[2 * j + 1], af, b2, b3);
                }
            }
            if (c + 2 < 4) {
                __syncthreads();
                uint32_t dstb = (c & 1) ? b1_base : b0_base;
                #pragma unroll
                for (int it = 0; it < 17; it++) {
                    int i = it * 256 + tid;
                    int rr = i >> 3, k4 = i & 7;
                    cp16(dstb + rr * AB_ROWB + k4 * 16,
                         &g_wb2[rr * 256 + (c + 2) * 64 + k4 * 8]);
                }
                CP_COMMIT();
            }
        }
        __syncthreads();

        {
            int row0 = mt * 16 + (lane >> 2);
            int cofs = (lane & 3) * 2;
            #pragma unroll
            for (int j = 0; j < 34; j++) {
                int col = nh * 272 + j * 8 + cofs;
                float bb0 = sbias[col], bb1 = sbias[col + 1];
                Out[row0 * OUT_PAD + col]           = acc[j][0] + bb0;
                Out[row0 * OUT_PAD + col + 1]       = acc[j][1] + bb1;
                Out[(row0 + 8) * OUT_PAD + col]     = acc[j][2] + bb0;
                Out[(row0 + 8) * OUT_PAD + col + 1] = acc[j][3] + bb1;
            }
        }
        __syncthreads();

        int node = tid >> 3, h = tid & 7;
        const float4* q0 = reinterpret_cast<const float4*>(
            &Out[(node * 2 + 0) * OUT_PAD + h * 32]);
        const float4* q1 = reinterpret_cast<const float4*>(
            &Out[(node * 2 + 1) * OUT_PAD + h * 32]);
        const float4* k0 = reinterpret_cast<const float4*>(
            &Out[(node * 2 + 0) * OUT_PAD + 256 + h * 32]);
        const float4* k1 = reinterpret_cast<const float4*>(
            &Out[(node * 2 + 1) * OUT_PAD + 256 + h * 32]);
        float s00 = 0.f, s01 = 0.f, s10 = 0.f, s11 = 0.f;
        #pragma unroll
        for (int d = 0; d < 8; d++) {
            float4 a0 = q0[d], a1 = q1[d], b0 = k0[d], b1 = k1[d];
            s00 += a0.x * b0.x + a0.y * b0.y + a0.z * b0.z + a0.w * b0.w;
            s01 += a0.x * b1.x + a0.y * b1.y + a0.z * b1.z + a0.w * b1.w;
            s10 += a1.x * b0.x + a1.y * b0.y + a1.z * b0.z + a1.w * b0.w;
            s11 += a1.x * b1.x + a1.y * b1.y + a1.z * b1.z + a1.w * b1.w;
        }
        const float scale = 0.17677669529663687f;
        s00 *= scale; s01 *= scale; s10 *= scale; s11 *= scale;
        float m0 = fmaxf(s00, s01), m1 = fmaxf(s10, s11);
        float e00 = expf(s00 - m0), e01 = expf(s01 - m0);
        float e10 = expf(s10 - m1), e11 = expf(s11 - m1);
        float d0 = e00 + e01, d1 = e10 + e11;
        float a00 = e00 / d0, a01 = e01 / d0;
        float a10 = e10 / d1, a11 = e11 / d1;
        float dv0 = Out[(node * 2 + 0) * OUT_PAD + 512 + h]
                  + Out[(node * 2 + 0) * OUT_PAD + 520 + h];
        float dv1 = Out[(node * 2 + 1) * OUT_PAD + 512 + h]
                  + Out[(node * 2 + 1) * OUT_PAD + 520 + h];
        float contrib = 0.5f * ((a00 + a10) * dv0 + (a01 + a11) * dv1);
        if (n0 + node >= n) contrib = 0.f;

        #pragma unroll
        for (int off = 16; off; off >>= 1)
            contrib += __shfl_xor_sync(0xffffffffu, contrib, off);
        if (lane == 0) red[wid] = contrib;
        __syncthreads();
        if (tid == 0) {
            float s = 0.f;
            #pragma unroll
            for (int w = 0; w < 8; w++) s += red[w];
            atomicAdd(&g_acc[0], s);
            __threadfence();
            int done = atomicAdd(&g_done[0], 1);
            if (done == nattn - 1) {
                out[0] = g_acc[0] / (float)n + g_konst[0];
            }
        }
    }
}

// ---------------- launch ----------------
extern "C" void kernel_launch(void* const* d_in, const int* in_sizes, int n_in,
                              void* d_out, int out_size) {
    const float* x   = (const float*)d_in[0];
    const int*   ei  = (const int*)d_in[1];
    const float* W_s = (const float*)d_in[2];
    const float* b_s = (const float*)d_in[3];
    const float* W_f = (const float*)d_in[4];
    const float* b_f = (const float*)d_in[5];
    const float* ipw = (const float*)d_in[6];
    const float* ipb = (const float*)d_in[7];
    const float* opw = (const float*)d_in[8];
    const float* opb = (const float*)d_in[9];
    const float* ow  = (const float*)d_in[10];
    const float* ob  = (const float*)d_in[11];

    int n = in_sizes[0] / FEAT;
    int E = in_sizes[1] / 2;
    int nb  = (n + 255) / 256;             // scan blocks
    int ndeg = (E + 255) / 256;            // degree/scatter blocks
    int nxc  = (n * 152 + 255) / 256;      // xconv blocks
    int nwc  = (544 * 128 + 255) / 256;    // wconv2 blocks
    int nwg  = (512 * 320 + 255) / 256;    // wgcn blocks
    int ngcn  = (n + 63) / 64;
    int nattn = (n + 31) / 32;

    k_init <<<nb + 1, 256>>>(ipw, ipb, opw, opb, ow, ob, n, nb);
    k_front<<<ndeg + nxc, 256>>>(ei, x, E, n, ndeg);
    k_scanA<<<nb, 256>>>(n);
    k_scanC<<<nb, 256>>>(nb, n);
    k_mid  <<<ndeg + nwc + nwg, 256>>>(ei, ipw, W_s, W_f, E, ndeg, nwc);
    k_gather<<<(n + 7) / 8, 256>>>(n);

    cudaFuncSetAttribute(k_tail, cudaFuncAttributeMaxDynamicSharedMemorySize, TAIL_SM_TOTAL);
    k_tail<<<ngcn + nattn, 256, TAIL_SM_TOTAL>>>(b_s, b_f, ipb, (float*)d_out,
                                                 n, ngcn, nattn);
}